// round 14
// baseline (speedup 1.0000x reference)
#include <cuda_runtime.h>
#include <cuda_bf16.h>
#include <cuda_fp16.h>
#include <math.h>
#include <stdint.h>

#define B_ 16
#define T_ 256
#define H_ 128
#define E_ 128
#define V_ 50000
#define VP_ 50176  /* padded vocab rows for guard-free staging */
#define G_ 512     /* 4*H */

// ---------------- scratch (no allocation allowed) ----------------
__device__ float g_xproj[(size_t)T_ * B_ * G_];          // 8 MB
__device__ float g_y0[(size_t)T_ * B_ * H_];             // layer0 out [T,B,H] fp32
__device__ __half g_ah[(size_t)B_ * T_ * H_];            // layer1 out hi fp16 [B,T,H]
__device__ __half g_al[(size_t)B_ * T_ * H_];            // layer1 out lo fp16 [B,T,H]
__device__ __half g_w16[(size_t)VP_ * H_];               // fc_w fp16 (padded)

// ---------------- helpers ----------------
static __device__ __forceinline__ unsigned long long pk2(float x, float y) {
    unsigned long long r;
    asm("mov.b64 %0, {%1, %2};" : "=l"(r) : "f"(x), "f"(y));
    return r;
}
static __device__ __forceinline__ float2 upk2(unsigned long long v) {
    float2 r;
    asm("mov.b64 {%0, %1}, %2;" : "=f"(r.x), "=f"(r.y) : "l"(v));
    return r;
}
static __device__ __forceinline__ unsigned long long ffma2(
    unsigned long long a, unsigned long long b, unsigned long long c) {
    unsigned long long d;
    asm("fma.rn.f32x2 %0, %1, %2, %3;" : "=l"(d) : "l"(a), "l"(b), "l"(c));
    return d;
}
static __device__ __forceinline__ uint32_t smem_u32(const void* p) {
    uint32_t a;
    asm("{ .reg .u64 t; cvta.to.shared.u64 t, %1; cvt.u32.u64 %0, t; }" : "=r"(a) : "l"(p));
    return a;
}

static __device__ __forceinline__ void ldsm4(uint32_t* r, uint32_t addr) {
    asm volatile("ldmatrix.sync.aligned.m8n8.x4.shared.b16 {%0,%1,%2,%3}, [%4];"
        : "=r"(r[0]), "=r"(r[1]), "=r"(r[2]), "=r"(r[3]) : "r"(addr));
}
static __device__ __forceinline__ void mma16816h(
    float* c, const uint32_t* a, uint32_t b0, uint32_t b1)
{
    asm volatile(
        "mma.sync.aligned.m16n8k16.row.col.f32.f16.f16.f32 "
        "{%0,%1,%2,%3}, {%4,%5,%6,%7}, {%8,%9}, {%0,%1,%2,%3};"
        : "+f"(c[0]), "+f"(c[1]), "+f"(c[2]), "+f"(c[3])
        : "r"(a[0]), "r"(a[1]), "r"(a[2]), "r"(a[3]), "r"(b0), "r"(b1));
}
static __device__ __forceinline__ void cpasync16(uint32_t dst, const void* src) {
    asm volatile("cp.async.cg.shared.global [%0], [%1], 16;" :: "r"(dst), "l"(src));
}

// swizzled byte offset inside a 128-row x 64-h16 (128B/row) smem tile
static __device__ __forceinline__ uint32_t tile_off(int row, int kb) {
    return (uint32_t)(row * 128 + ((kb ^ (row & 7)) << 4));
}

#define MBAR_INIT(a, c) asm volatile("mbarrier.init.shared.b64 [%0], %1;" :: "r"((uint32_t)(a)), "r"((uint32_t)(c)) : "memory")

#define WAIT_PARITY(mbar_addr, parity) do { \
    uint32_t _mb = (uint32_t)(mbar_addr); \
    uint32_t _pr = (uint32_t)(parity); \
    asm volatile( \
        "{\n\t.reg .pred P1;\n\t" \
        "WAIT_LOOP_%=:\n\t" \
        "mbarrier.try_wait.parity.acquire.cta.shared::cta.b64 P1, [%0], %1, 0x989680;\n\t" \
        "@P1 bra.uni WAIT_DONE_%=;\n\t" \
        "bra.uni WAIT_LOOP_%=;\n\t" \
        "WAIT_DONE_%=:\n\t}" \
        :: "r"(_mb), "r"(_pr) : "memory"); \
} while (0)

extern __shared__ char dynsm[];

// =====================================================================
// proj GEMM: out[r][g] = dot(A(r,:), Wih[g,:]) + bih + bhh
// =====================================================================
#define PROJ_SMEM (64 * 132 * 4 + 128 * 65 * 4)

__global__ __launch_bounds__(256) void proj_kernel(
    const float* __restrict__ Asrc, const int* __restrict__ xidx,
    const float* __restrict__ Wih, const float* __restrict__ bih,
    const float* __restrict__ bhh, float* __restrict__ out)
{
    float* smf = reinterpret_cast<float*>(dynsm);
    float (*As)[132] = reinterpret_cast<float(*)[132]>(smf);
    float (*Ws)[65]  = reinterpret_cast<float(*)[65]>(smf + 64 * 132);

    const int m0 = blockIdx.y * 64;
    const int n0 = blockIdx.x * 64;
    const int tid = threadIdx.x;

    for (int i = tid; i < 64 * 32; i += 256) {
        int r = i >> 5, c4 = (i & 31) * 4;
        const float* arow;
        if (xidx) {
            int gr = m0 + r;
            int b = gr & 15, t = gr >> 4;
            arow = Asrc + (size_t)xidx[b * T_ + t] * E_;
        } else {
            arow = Asrc + (size_t)(m0 + r) * H_;
        }
        float4 v = *reinterpret_cast<const float4*>(arow + c4);
        *reinterpret_cast<float4*>(&As[r][c4]) = v;
    }
    for (int i = tid; i < 64 * 32; i += 256) {
        int n = i >> 5, c4 = (i & 31) * 4;
        float4 v = *reinterpret_cast<const float4*>(Wih + (size_t)(n0 + n) * 128 + c4);
        Ws[c4 + 0][n] = v.x; Ws[c4 + 1][n] = v.y;
        Ws[c4 + 2][n] = v.z; Ws[c4 + 3][n] = v.w;
    }
    __syncthreads();

    const int tx = tid & 15, ty = tid >> 4;
    float acc[4][4] = {};
    #pragma unroll 8
    for (int k = 0; k < 128; k++) {
        float a[4], w[4];
        #pragma unroll
        for (int i = 0; i < 4; i++) a[i] = As[ty * 4 + i][k];
        #pragma unroll
        for (int j = 0; j < 4; j++) w[j] = Ws[k][tx * 4 + j];
        #pragma unroll
        for (int i = 0; i < 4; i++)
            #pragma unroll
            for (int j = 0; j < 4; j++)
                acc[i][j] = fmaf(a[i], w[j], acc[i][j]);
    }

    #pragma unroll
    for (int j = 0; j < 4; j++) {
        int n = n0 + tx * 4 + j;
        float bv = bih[n] + bhh[n];
        #pragma unroll
        for (int i = 0; i < 4; i++)
            out[(size_t)(m0 + ty * 4 + i) * G_ + n] = acc[i][j] + bv;
    }
}

// =====================================================================
// LSTM recurrence — cluster of 4 CTAs per batch element, weights in regs,
// gate exchange via st.async + mbarrier (no per-step cluster barrier).
// grid = 64 CTAs (16 batch x 4 gate-types), 128 threads each.
// Each CTA's mbar[p] completes after 512 stores x 4B = 2048 tx bytes
// plus one arrive (tid0's arrive.expect_tx).
// =====================================================================
__global__ __launch_bounds__(128, 1) __cluster_dims__(4, 1, 1)
void lstm_cluster(const float* __restrict__ xproj, const float* __restrict__ Whh,
                  float* __restrict__ y, __half* __restrict__ yh,
                  __half* __restrict__ yl, int layer,
                  float* __restrict__ h_out, float* __restrict__ c_out)
{
    __shared__ __align__(16) float hs[H_];
    __shared__ __align__(16) float gs[2][G_];
    __shared__ __align__(8) unsigned long long mbar[2];
    const int tid = threadIdx.x;
    const int b = blockIdx.x >> 2;
    uint32_t rank;
    asm("mov.u32 %0, %%cluster_ctarank;" : "=r"(rank));
    const int row = (int)rank * H_ + tid;

    // gate row weights -> registers, packed f32x2
    unsigned long long wp[64];
    {
        const float4* w4 = reinterpret_cast<const float4*>(Whh + (size_t)row * H_);
        #pragma unroll
        for (int k = 0; k < 32; k++) {
            float4 v = w4[k];
            wp[2 * k]     = pk2(v.x, v.y);
            wp[2 * k + 1] = pk2(v.z, v.w);
        }
    }

    // peer addresses: gs[p][row] and mbar[p] in each cluster CTA
    uint32_t pg[2][4], pm[2][4];
    uint32_t lmbar[2];
    lmbar[0] = smem_u32(&mbar[0]);
    lmbar[1] = smem_u32(&mbar[1]);
    {
        uint32_t g0 = smem_u32(&gs[0][row]);
        uint32_t g1 = smem_u32(&gs[1][row]);
        #pragma unroll
        for (int r = 0; r < 4; r++) {
            asm("mapa.shared::cluster.u32 %0, %1, %2;" : "=r"(pg[0][r]) : "r"(g0), "r"(r));
            asm("mapa.shared::cluster.u32 %0, %1, %2;" : "=r"(pg[1][r]) : "r"(g1), "r"(r));
            asm("mapa.shared::cluster.u32 %0, %1, %2;" : "=r"(pm[0][r]) : "r"(lmbar[0]), "r"(r));
            asm("mapa.shared::cluster.u32 %0, %1, %2;" : "=r"(pm[1][r]) : "r"(lmbar[1]), "r"(r));
        }
    }

    if (tid == 0) {
        MBAR_INIT(lmbar[0], 1);
        MBAR_INIT(lmbar[1], 1);
    }
    hs[tid] = 0.f;
    __syncthreads();
    // all mbars initialized cluster-wide before any st.async may target them
    asm volatile("barrier.cluster.arrive.aligned;" ::: "memory");
    asm volatile("barrier.cluster.wait.aligned;" ::: "memory");

    float c = 0.f;
    int p = 0, ph0 = 0, ph1 = 0;
    for (int t = 0; t < T_; t++) {
        if (tid == 0) {
            asm volatile("mbarrier.arrive.expect_tx.shared.b64 _, [%0], %1;"
                :: "r"(lmbar[p]), "r"(2048u) : "memory");
        }
        float xv = xproj[((size_t)t * B_ + b) * G_ + row];

        unsigned long long a0 = 0ull, a1 = 0ull;
        const ulonglong2* h2 = reinterpret_cast<const ulonglong2*>(hs);
        #pragma unroll
        for (int k = 0; k < 32; k++) {
            ulonglong2 hv = h2[k];
            a0 = ffma2(wp[2 * k],     hv.x, a0);
            a1 = ffma2(wp[2 * k + 1], hv.y, a1);
        }
        float2 s0 = upk2(a0), s1 = upk2(a1);
        float gval = (s0.x + s0.y) + (s1.x + s1.y) + xv;

        // broadcast my gate value into gs[p][row] of all 4 cluster CTAs
        uint32_t gbits = __float_as_uint(gval);
        #pragma unroll
        for (int r = 0; r < 4; r++) {
            asm volatile(
                "st.async.weak.shared::cluster.mbarrier::complete_tx::bytes.b32 [%0], %1, [%2];"
                :: "r"(pg[p][r]), "r"(gbits), "r"(pm[p][r]) : "memory");
        }

        WAIT_PARITY(lmbar[p], (p == 0) ? ph0 : ph1);
        if (p == 0) ph0 ^= 1; else ph1 ^= 1;

        // redundant elementwise update (all CTAs, deterministic)
        float gi = gs[p][tid];
        float gf = gs[p][H_ + tid];
        float gg = gs[p][2 * H_ + tid];
        float go = gs[p][3 * H_ + tid];
        float iv = __fdividef(1.f, 1.f + __expf(-gi));
        float fv = __fdividef(1.f, 1.f + __expf(-gf));
        float e2 = __expf(2.f * gg);
        float gt = 1.f - __fdividef(2.f, e2 + 1.f);
        float ov = __fdividef(1.f, 1.f + __expf(-go));
        c = fv * c + iv * gt;
        float ec = __expf(2.f * c);
        float th = 1.f - __fdividef(2.f, ec + 1.f);
        float h = ov * th;
        hs[tid] = h;

        if (rank == 0) {
            if (layer == 0) {
                y[((size_t)t * B_ + b) * H_ + tid] = h;
            } else {
                __half hh = __float2half_rn(h);
                size_t r = ((size_t)b * T_ + t) * H_ + tid;
                yh[r] = hh;
                yl[r] = __float2half_rn(h - __half2float(hh));
            }
        }
        __syncthreads();
        p ^= 1;
    }

    if (rank == 0) {
        h_out[b * H_ + tid] = hs[tid];
        c_out[b * H_ + tid] = c;
    }
    // no CTA may exit while a peer's st.async toward it could be in flight
    asm volatile("barrier.cluster.arrive.aligned;" ::: "memory");
    asm volatile("barrier.cluster.wait.aligned;" ::: "memory");
}

// =====================================================================
// W conversion: fc_w fp32 [V,H] -> fp16, padded to VP_ rows.
// =====================================================================
__global__ __launch_bounds__(256) void wconv_kernel(
    const float* __restrict__ W, __half* __restrict__ W16)
{
    size_t idx = (size_t)blockIdx.x * 256 + threadIdx.x;   // one float4 each
    if (idx >= (size_t)VP_ * H_ / 4) return;
    float4 v = (idx < (size_t)V_ * H_ / 4)
        ? reinterpret_cast<const float4*>(W)[idx]
        : make_float4(0.f, 0.f, 0.f, 0.f);
    __half2 p0 = __floats2half2_rn(v.x, v.y);
    __half2 p1 = __floats2half2_rn(v.z, v.w);
    reinterpret_cast<__half2*>(W16)[2 * idx]     = p0;
    reinterpret_cast<__half2*>(W16)[2 * idx + 1] = p1;
}

// =====================================================================
// FC: logits = y1 @ fc_w^T + fc_b via mma.sync fp16 2-product split
// (virtual K = 256 = [Ah | Al] against one fp16 W).
// CTA tile 128x128, 8 warps (warp tile 32x64). All operands staged once
// (96 KB smem), zero mainloop syncs. Fragment addressing identical to the
// verified R13 kernel.
// smem: W half0 16K | W half1 16K | Ah0 16K | Ah1 16K | Al0 16K | Al1 16K |
//       bias 512B
// =====================================================================
#define FC2_SMEM (98304 + 512)

__global__ __launch_bounds__(256, 2) void fc_mma_kernel(
    const __half* __restrict__ Ah, const __half* __restrict__ Al,
    const __half* __restrict__ W16, const float* __restrict__ bias,
    float* __restrict__ out)
{
    char* smb = dynsm;
    const uint32_t sb = smem_u32(smb);
    const int tid = threadIdx.x;
    const int lane = tid & 31, wid = tid >> 5;
    const int n0 = blockIdx.x * 128;
    const int m0 = blockIdx.y * 128;
    const int m_off = (wid >> 1) * 32;   // warp m offset (0..96)
    const int n_off = (wid & 1) * 64;    // warp n offset (0/64)
    float* sbias = reinterpret_cast<float*>(smb + 98304);

    if (tid < 128) sbias[tid] = (n0 + tid < V_) ? bias[n0 + tid] : 0.f;

    // stage all 6 16KB sub-tiles: W0,W1,Ah0,Ah1,Al0,Al1
    #pragma unroll
    for (int stile = 0; stile < 6; stile++) {
        const int kh = stile & 1;
        const int which = stile >> 1;
        const __half* bsrc = (which == 0) ? W16 : ((which == 1) ? Ah : Al);
        const int rowbase = (which == 0) ? n0 : m0;
        const uint32_t dstb = sb + (uint32_t)stile * 16384;
        #pragma unroll
        for (int ii = 0; ii < 4; ii++) {
            int i = tid + ii * 256;
            int row = i >> 3, kb = i & 7;
            cpasync16(dstb + tile_off(row, kb),
                      bsrc + (size_t)(rowbase + row) * H_ + kh * 64 + kb * 8);
        }
    }
    asm volatile("cp.async.commit_group;" ::: "memory");
    asm volatile("cp.async.wait_group 0;" ::: "memory");
    __syncthreads();

    float acc[2][8][4];
    #pragma unroll
    for (int mt = 0; mt < 2; mt++)
        #pragma unroll
        for (int nt = 0; nt < 8; nt++)
            #pragma unroll
            for (int q = 0; q < 4; q++) acc[mt][nt][q] = 0.f;

    #pragma unroll
    for (int prod = 0; prod < 2; prod++) {
        #pragma unroll
        for (int kh = 0; kh < 2; kh++) {
            uint32_t ab = sb + 32768 + (uint32_t)prod * 32768 + (uint32_t)kh * 16384;
            uint32_t wb = sb + (uint32_t)kh * 16384;
            #pragma unroll
            for (int s = 0; s < 4; s++) {
                uint32_t afr[2][4];
                #pragma unroll
                for (int mt = 0; mt < 2; mt++) {
                    int row = m_off + mt * 16 + (lane & 15);
                    int kb = s * 2 + (lane >> 4);
                    ldsm4(afr[mt], ab + tile_off(row, kb));
                }
                uint32_t bfr[4][4];
                #pragma unroll
                for (int nq = 0; nq < 4; nq++) {
                    int row = n_off + nq * 16 + (lane & 7) + ((lane >> 3) & 1) * 8;
                    int kb = s * 2 + (lane >> 4);
                    ldsm4(bfr[nq], wb + tile_off(row, kb));
                }
                #pragma unroll
                for (int mt = 0; mt < 2; mt++)
                    #pragma unroll
                    for (int nq = 0; nq < 4; nq++) {
                        mma16816h(acc[mt][nq * 2],     afr[mt], bfr[nq][0], bfr[nq][2]);
                        mma16816h(acc[mt][nq * 2 + 1], afr[mt], bfr[nq][1], bfr[nq][3]);
                    }
            }
        }
    }

    // epilogue: c0,c1 -> (row, col..col+1); c2,c3 -> (row+8, same cols)
    #pragma unroll
    for (int mt = 0; mt < 2; mt++) {
        int r0 = m0 + m_off + mt * 16 + (lane >> 2);
        #pragma unroll
        for (int nt = 0; nt < 8; nt++) {
            int nl = n_off + nt * 8 + (lane & 3) * 2;
            int cN = n0 + nl;
            if (cN < V_) {
                float b0 = sbias[nl], b1 = sbias[nl + 1];
                float2 o;
                o.x = acc[mt][nt][0] + b0; o.y = acc[mt][nt][1] + b1;
                *reinterpret_cast<float2*>(out + (size_t)r0 * V_ + cN) = o;
                o.x = acc[mt][nt][2] + b0; o.y = acc[mt][nt][3] + b1;
                *reinterpret_cast<float2*>(out + (size_t)(r0 + 8) * V_ + cN) = o;
            }
        }
    }
}

// =====================================================================
// launch
// =====================================================================
extern "C" void kernel_launch(void* const* d_in, const int* in_sizes, int n_in,
                              void* d_out, int out_size)
{
    const int*   x    = (const int*)  d_in[0];
    const float* emb  = (const float*)d_in[1];
    const float* Wih0 = (const float*)d_in[2];
    const float* Whh0 = (const float*)d_in[3];
    const float* bih0 = (const float*)d_in[4];
    const float* bhh0 = (const float*)d_in[5];
    const float* Wih1 = (const float*)d_in[6];
    const float* Whh1 = (const float*)d_in[7];
    const float* bih1 = (const float*)d_in[8];
    const float* bhh1 = (const float*)d_in[9];
    const float* fcw  = (const float*)d_in[10];
    const float* fcb  = (const float*)d_in[11];
    float* out = (float*)d_out;

    float *xproj, *y0;
    __half *ah, *al, *w16;
    cudaGetSymbolAddress((void**)&xproj, g_xproj);
    cudaGetSymbolAddress((void**)&y0, g_y0);
    cudaGetSymbolAddress((void**)&ah, g_ah);
    cudaGetSymbolAddress((void**)&al, g_al);
    cudaGetSymbolAddress((void**)&w16, g_w16);

    cudaFuncSetAttribute(proj_kernel, cudaFuncAttributeMaxDynamicSharedMemorySize, PROJ_SMEM);
    cudaFuncSetAttribute(fc_mma_kernel, cudaFuncAttributeMaxDynamicSharedMemorySize, FC2_SMEM);

    // output layout: logits [B,T,V] || h [L,B,H] || c [L,B,H]
    const size_t NL = (size_t)B_ * T_ * V_;
    float* h_base = out + NL;
    float* c_base = out + NL + 2 * B_ * H_;

    // W conversion (independent of LSTM chain)
    wconv_kernel<<<(VP_ * H_ / 4 + 255) / 256, 256>>>(fcw, w16);
    // layer 0
    proj_kernel<<<dim3(8, 64), 256, PROJ_SMEM>>>(emb, x, Wih0, bih0, bhh0, xproj);
    lstm_cluster<<<64, 128>>>(xproj, Whh0, y0, ah, al, 0, h_base, c_base);
    // layer 1
    proj_kernel<<<dim3(8, 64), 256, PROJ_SMEM>>>(y0, nullptr, Wih1, bih1, bhh1, xproj);
    lstm_cluster<<<64, 128>>>(xproj, Whh1, y0, ah, al, 1, h_base + B_ * H_, c_base + B_ * H_);
    // output projection (HMMA fp16 2-product split, shared W tile)
    fc_mma_kernel<<<dim3((V_ + 127) / 128, 32), 256, FC2_SMEM>>>(ah, al, w16, fcb, out);
}